// round 1
// baseline (speedup 1.0000x reference)
#include <cuda_runtime.h>
#include <cstdint>

// Shapes (fixed by the problem): x (8,3,1024,1024) f32 -> out (8,3,512,512) f32
// Inputs: d_in[0]=x, d_in[1]=w0 (K0*512 f32), d_in[2]=fov0 (K0*512 i32),
//         d_in[3]=w1 (K1*512 f32), d_in[4]=fov1 (K1*512 i32)
// Separable: vertical taps (dim2) use w0/fov0, horizontal taps (dim3) use w1/fov1.

#define BC     24          // 8*3
#define IN_H   1024
#define IN_W   1024
#define OUT_H  512
#define OUT_W  512

// Scratch: horizontal-pass intermediate, shape (BC, IN_H, OUT_W) = 48 MB
__device__ float g_tmp[(size_t)BC * IN_H * OUT_W];

// ---------------------------------------------------------------------------
// Pass 1: horizontal resample.  One block per input row (bc*IN_H + h).
// Stage the 1024-float row in shared memory, then each of 128 threads
// produces 4 consecutive outputs (vectorized weight/index loads).
// ---------------------------------------------------------------------------
__global__ __launch_bounds__(128)
void hpass_kernel(const float* __restrict__ x,
                  const float* __restrict__ w1,
                  const int*   __restrict__ fov1,
                  int K1)
{
    __shared__ float srow[IN_W];

    const int row = blockIdx.x;                 // 0 .. BC*IN_H-1
    const float* xr = x + (size_t)row * IN_W;

    // cooperative vectorized row load: 256 float4, 128 threads -> 2 each
    {
        const float4* xr4 = reinterpret_cast<const float4*>(xr);
        float4* s4 = reinterpret_cast<float4*>(srow);
        s4[threadIdx.x]       = xr4[threadIdx.x];
        s4[threadIdx.x + 128] = xr4[threadIdx.x + 128];
    }
    __syncthreads();

    const int t = threadIdx.x;                  // 0..127, covers ow = 4t..4t+3
    float a0 = 0.f, a1 = 0.f, a2 = 0.f, a3 = 0.f;

    for (int j = 0; j < K1; ++j) {
        const float4 wj = reinterpret_cast<const float4*>(w1 + j * OUT_W)[t];
        const int4   fj = reinterpret_cast<const int4*>(fov1 + j * OUT_W)[t];
        a0 += wj.x * srow[fj.x];
        a1 += wj.y * srow[fj.y];
        a2 += wj.z * srow[fj.z];
        a3 += wj.w * srow[fj.w];
    }

    float4 r; r.x = a0; r.y = a1; r.z = a2; r.w = a3;
    reinterpret_cast<float4*>(g_tmp + (size_t)row * OUT_W)[t] = r;
}

// ---------------------------------------------------------------------------
// Pass 2: vertical resample.  One block per (oh, bc).  128 threads, each
// handles one float4 along ow.  Per-tap index/weight are uniform across the
// block (broadcast loads); row reads are fully coalesced float4.
// ---------------------------------------------------------------------------
__global__ __launch_bounds__(128)
void vpass_kernel(const float* __restrict__ w0,
                  const int*   __restrict__ fov0,
                  float*       __restrict__ out,
                  int K0)
{
    const int oh = blockIdx.x;                  // 0..OUT_H-1
    const int bc = blockIdx.y;                  // 0..BC-1
    const int t  = threadIdx.x;                 // float4 lane along ow

    const float* tbase = g_tmp + (size_t)bc * IN_H * OUT_W;

    float4 acc; acc.x = acc.y = acc.z = acc.w = 0.f;

    for (int i = 0; i < K0; ++i) {
        const int   r = fov0[i * OUT_H + oh];
        const float w = w0[i * OUT_H + oh];
        const float4 v = reinterpret_cast<const float4*>(tbase + (size_t)r * OUT_W)[t];
        acc.x += w * v.x;
        acc.y += w * v.y;
        acc.z += w * v.z;
        acc.w += w * v.w;
    }

    reinterpret_cast<float4*>(out + ((size_t)bc * OUT_H + oh) * OUT_W)[t] = acc;
}

// ---------------------------------------------------------------------------

extern "C" void kernel_launch(void* const* d_in, const int* in_sizes, int n_in,
                              void* d_out, int out_size)
{
    const float* x    = (const float*)d_in[0];
    const float* w0   = (const float*)d_in[1];
    const int*   fov0 = (const int*)  d_in[2];
    const float* w1   = (const float*)d_in[3];
    const int*   fov1 = (const int*)  d_in[4];
    float*       out  = (float*)d_out;

    const int K0 = in_sizes[1] / OUT_H;   // taps for dim 2 (vertical)
    const int K1 = in_sizes[3] / OUT_W;   // taps for dim 3 (horizontal)

    hpass_kernel<<<BC * IN_H, 128>>>(x, w1, fov1, K1);

    dim3 vgrid(OUT_H, BC);
    vpass_kernel<<<vgrid, 128>>>(w0, fov0, out, K0);
}

// round 2
// speedup vs baseline: 1.8424x; 1.8424x over previous
#include <cuda_runtime.h>
#include <cstdint>

// x (8,3,1024,1024) f32 -> out (8,3,512,512) f32
// d_in: [0]=x, [1]=w0 (K0*512), [2]=fov0 (K0*512 i32)  -> dim2 (H, vertical)
//       [3]=w1 (K1*512), [4]=fov1 (K1*512 i32)         -> dim3 (W, horizontal)
// Strategy: vertical pass FIRST (coalesced, no gather), then horizontal pass
// on 1024-wide intermediate rows with 2-way-conflict smem gather.

#define BC     24
#define IN_H   1024
#define IN_W   1024
#define OUT_H  512
#define OUT_W  512
#define OH_PER_BLK 4

// Scratch: vertical-pass intermediate, shape (BC, OUT_H, IN_W) = 50.3 MB
__device__ float g_tmp[(size_t)BC * OUT_H * IN_W];

// ---------------------------------------------------------------------------
// Pass A: vertical resample at full width.
// Block = (oh group of 4, bc). 256 threads, thread t owns float4 column chunk.
// Taps are uniform per output row -> all loads fully coalesced float4.
// Tap-window overlap between the 4 rows is captured by L1 within the block.
// ---------------------------------------------------------------------------
__global__ __launch_bounds__(256)
void vpass_kernel(const float* __restrict__ x,
                  const float* __restrict__ w0,
                  const int*   __restrict__ fov0,
                  int K0)
{
    const int t   = threadIdx.x;            // float4 chunk: cols 4t..4t+3
    const int bc  = blockIdx.y;
    const int oh0 = blockIdx.x * OH_PER_BLK;

    const float4* xb = reinterpret_cast<const float4*>(x + (size_t)bc * IN_H * IN_W);

    float4 acc[OH_PER_BLK];
#pragma unroll
    for (int i = 0; i < OH_PER_BLK; ++i) { acc[i].x = acc[i].y = acc[i].z = acc[i].w = 0.f; }

    for (int j = 0; j < K0; ++j) {
#pragma unroll
        for (int i = 0; i < OH_PER_BLK; ++i) {
            const int   oh = oh0 + i;
            const int   r  = fov0[j * OUT_H + oh];
            const float w  = w0  [j * OUT_H + oh];
            const float4 v = xb[(size_t)r * (IN_W / 4) + t];
            acc[i].x += w * v.x;
            acc[i].y += w * v.y;
            acc[i].z += w * v.z;
            acc[i].w += w * v.w;
        }
    }

    float4* tb = reinterpret_cast<float4*>(g_tmp + (size_t)bc * OUT_H * IN_W);
#pragma unroll
    for (int i = 0; i < OH_PER_BLK; ++i)
        tb[(size_t)(oh0 + i) * (IN_W / 4) + t] = acc[i];
}

// ---------------------------------------------------------------------------
// Pass B: horizontal resample on (BC*OUT_H) rows of 1024.
// One block per row; stage row in smem; thread t owns ow = t and t+256
// (strided) so the gather is stride-2 floats -> only 2-way bank conflicts.
// ---------------------------------------------------------------------------
__global__ __launch_bounds__(256)
void hpass_kernel(const float* __restrict__ w1,
                  const int*   __restrict__ fov1,
                  float*       __restrict__ out,
                  int K1)
{
    __shared__ float srow[IN_W];

    const int row = blockIdx.x;              // 0 .. BC*OUT_H-1
    const int t   = threadIdx.x;

    // stage 1024 floats: 256 threads x 1 float4
    reinterpret_cast<float4*>(srow)[t] =
        reinterpret_cast<const float4*>(g_tmp + (size_t)row * IN_W)[t];
    __syncthreads();

    float a0 = 0.f, a1 = 0.f;
    for (int j = 0; j < K1; ++j) {
        const float* wrow = w1   + j * OUT_W;
        const int*   frow = fov1 + j * OUT_W;
        const float w_a = wrow[t];
        const float w_b = wrow[t + 256];
        const int   f_a = frow[t];
        const int   f_b = frow[t + 256];
        a0 += w_a * srow[f_a];
        a1 += w_b * srow[f_b];
    }

    float* orow = out + (size_t)row * OUT_W;
    orow[t]       = a0;
    orow[t + 256] = a1;
}

// ---------------------------------------------------------------------------

extern "C" void kernel_launch(void* const* d_in, const int* in_sizes, int n_in,
                              void* d_out, int out_size)
{
    const float* x    = (const float*)d_in[0];
    const float* w0   = (const float*)d_in[1];
    const int*   fov0 = (const int*)  d_in[2];
    const float* w1   = (const float*)d_in[3];
    const int*   fov1 = (const int*)  d_in[4];
    float*       out  = (float*)d_out;

    const int K0 = in_sizes[1] / OUT_H;   // vertical taps
    const int K1 = in_sizes[3] / OUT_W;   // horizontal taps

    dim3 vgrid(OUT_H / OH_PER_BLK, BC);
    vpass_kernel<<<vgrid, 256>>>(x, w0, fov0, K0);

    hpass_kernel<<<BC * OUT_H, 256>>>(w1, fov1, out, K1);
}

// round 3
// speedup vs baseline: 2.4639x; 1.3373x over previous
#include <cuda_runtime.h>
#include <cstdint>

// x (8,3,1024,1024) f32 -> out (8,3,512,512) f32
// d_in: [0]=x, [1]=w0 (K0*512), [2]=fov0 (K0*512 i32)  -> dim2 (H, vertical)
//       [3]=w1 (K1*512), [4]=fov1 (K1*512 i32)         -> dim3 (W, horizontal)
//
// Fully fused separable resize. Block = (bc, group of G output rows).
//  Phase 1 (vertical): coalesced float4 reads of K0 input rows per output row,
//    weighted-accumulated into a G x 1024 smem tile. Input-row overlap inside
//    the group is served by L1.
//  Phase 2 (horizontal): per tap, load (w, fov) ONCE per thread and reuse
//    across all G rows (kills the redundant weight traffic that bound R2's
//    hpass). Gather stride-2 in smem -> only 2-way bank conflicts.

#define BC     24
#define IN_H   1024
#define IN_W   1024
#define OUT_H  512
#define OUT_W  512
#define G      8           // output rows per block

__global__ __launch_bounds__(256)
void fused_resize_kernel(const float* __restrict__ x,
                         const float* __restrict__ w0,
                         const int*   __restrict__ fov0,
                         const float* __restrict__ w1,
                         const int*   __restrict__ fov1,
                         float*       __restrict__ out,
                         int K0, int K1)
{
    __shared__ float tile[G][IN_W];              // 32 KB

    const int t   = threadIdx.x;                 // 0..255
    const int bc  = blockIdx.y;
    const int oh0 = blockIdx.x * G;

    const float4* xb = reinterpret_cast<const float4*>(x + (size_t)bc * IN_H * IN_W);

    // ---------------- Phase 1: vertical resample into smem tile -------------
#pragma unroll 2
    for (int i = 0; i < G; ++i) {
        const int oh = oh0 + i;
        float ax = 0.f, ay = 0.f, az = 0.f, aw = 0.f;
        for (int j = 0; j < K0; ++j) {
            const int   r = fov0[j * OUT_H + oh];   // broadcast across block
            const float w = w0  [j * OUT_H + oh];
            const float4 v = xb[(size_t)r * (IN_W / 4) + t];
            ax += w * v.x;
            ay += w * v.y;
            az += w * v.z;
            aw += w * v.w;
        }
        float4 r4; r4.x = ax; r4.y = ay; r4.z = az; r4.w = aw;
        reinterpret_cast<float4*>(tile[i])[t] = r4;
    }
    __syncthreads();

    // ---------------- Phase 2: horizontal resample from smem ----------------
    float a0[G], a1[G];
#pragma unroll
    for (int i = 0; i < G; ++i) { a0[i] = 0.f; a1[i] = 0.f; }

    for (int j = 0; j < K1; ++j) {
        const float w_a = w1  [j * OUT_W + t];
        const float w_b = w1  [j * OUT_W + t + 256];
        const int   f_a = fov1[j * OUT_W + t];
        const int   f_b = fov1[j * OUT_W + t + 256];
#pragma unroll
        for (int i = 0; i < G; ++i) {
            a0[i] += w_a * tile[i][f_a];
            a1[i] += w_b * tile[i][f_b];
        }
    }

#pragma unroll
    for (int i = 0; i < G; ++i) {
        float* orow = out + ((size_t)bc * OUT_H + oh0 + i) * OUT_W;
        orow[t]       = a0[i];
        orow[t + 256] = a1[i];
    }
}

// ---------------------------------------------------------------------------

extern "C" void kernel_launch(void* const* d_in, const int* in_sizes, int n_in,
                              void* d_out, int out_size)
{
    const float* x    = (const float*)d_in[0];
    const float* w0   = (const float*)d_in[1];
    const int*   fov0 = (const int*)  d_in[2];
    const float* w1   = (const float*)d_in[3];
    const int*   fov1 = (const int*)  d_in[4];
    float*       out  = (float*)d_out;

    const int K0 = in_sizes[1] / OUT_H;   // vertical taps
    const int K1 = in_sizes[3] / OUT_W;   // horizontal taps

    dim3 grid(OUT_H / G, BC);
    fused_resize_kernel<<<grid, 256>>>(x, w0, fov0, w1, fov1, out, K0, K1);
}

// round 4
// speedup vs baseline: 2.6591x; 1.0793x over previous
#include <cuda_runtime.h>
#include <cstdint>

// x (8,3,1024,1024) f32 -> out (8,3,512,512) f32
// d_in: [0]=x, [1]=w0 (K0*512), [2]=fov0 (K0*512 i32)  -> dim2 (H, vertical)
//       [3]=w1 (K1*512), [4]=fov1 (K1*512 i32)         -> dim3 (W, horizontal)
//
// Fused separable resize, R4: parity-split smem tile.
// Column f lives at perm(f) = (f>>1) + (f&1)*512. For a fixed horizontal tap,
// warp lanes access stride-2 input columns -> constant parity -> stride-1 in
// the permuted layout -> conflict-free LDS (was 2-way conflicted).

#define BC     24
#define IN_H   1024
#define IN_W   1024
#define OUT_H  512
#define OUT_W  512
#define G      8           // output rows per block

__global__ __launch_bounds__(256)
void fused_resize_kernel(const float* __restrict__ x,
                         const float* __restrict__ w0,
                         const int*   __restrict__ fov0,
                         const float* __restrict__ w1,
                         const int*   __restrict__ fov1,
                         float*       __restrict__ out,
                         int K0, int K1)
{
    __shared__ float tile[G][IN_W];              // 32 KB, parity-permuted

    const int t   = threadIdx.x;                 // 0..255
    const int bc  = blockIdx.y;
    const int oh0 = blockIdx.x * G;

    const float4* xb = reinterpret_cast<const float4*>(x + (size_t)bc * IN_H * IN_W);

    // ---------------- Phase 1: vertical resample into permuted smem tile ----
#pragma unroll 2
    for (int i = 0; i < G; ++i) {
        const int oh = oh0 + i;
        float ax = 0.f, ay = 0.f, az = 0.f, aw = 0.f;
        for (int j = 0; j < K0; ++j) {
            const int   r = fov0[j * OUT_H + oh];   // broadcast across block
            const float w = w0  [j * OUT_H + oh];
            const float4 v = xb[(size_t)r * (IN_W / 4) + t];
            ax += w * v.x;   // col 4t   -> perm word 2t
            ay += w * v.y;   // col 4t+1 -> perm word 512+2t
            az += w * v.z;   // col 4t+2 -> perm word 2t+1
            aw += w * v.w;   // col 4t+3 -> perm word 512+2t+1
        }
        float2 e; e.x = ax; e.y = az;
        float2 o; o.x = ay; o.y = aw;
        reinterpret_cast<float2*>(tile[i])[t]       = e;   // even cols, stride-1
        reinterpret_cast<float2*>(tile[i] + 512)[t] = o;   // odd cols,  stride-1
    }
    __syncthreads();

    // ---------------- Phase 2: horizontal resample from permuted smem -------
    float a0[G], a1[G];
#pragma unroll
    for (int i = 0; i < G; ++i) { a0[i] = 0.f; a1[i] = 0.f; }

    for (int j = 0; j < K1; ++j) {
        const float w_a = w1  [j * OUT_W + t];
        const float w_b = w1  [j * OUT_W + t + 256];
        const int   f_a = fov1[j * OUT_W + t];
        const int   f_b = fov1[j * OUT_W + t + 256];
        // permuted indices, computed once per tap, reused across G rows
        const int p_a = (f_a >> 1) + ((f_a & 1) << 9);
        const int p_b = (f_b >> 1) + ((f_b & 1) << 9);
#pragma unroll
        for (int i = 0; i < G; ++i) {
            a0[i] += w_a * tile[i][p_a];
            a1[i] += w_b * tile[i][p_b];
        }
    }

#pragma unroll
    for (int i = 0; i < G; ++i) {
        float* orow = out + ((size_t)bc * OUT_H + oh0 + i) * OUT_W;
        orow[t]       = a0[i];
        orow[t + 256] = a1[i];
    }
}

// ---------------------------------------------------------------------------

extern "C" void kernel_launch(void* const* d_in, const int* in_sizes, int n_in,
                              void* d_out, int out_size)
{
    const float* x    = (const float*)d_in[0];
    const float* w0   = (const float*)d_in[1];
    const int*   fov0 = (const int*)  d_in[2];
    const float* w1   = (const float*)d_in[3];
    const int*   fov1 = (const int*)  d_in[4];
    float*       out  = (float*)d_out;

    const int K0 = in_sizes[1] / OUT_H;   // vertical taps
    const int K1 = in_sizes[3] / OUT_W;   // horizontal taps

    dim3 grid(OUT_H / G, BC);
    fused_resize_kernel<<<grid, 256>>>(x, w0, fov0, w1, fov1, out, K0, K1);
}

// round 5
// speedup vs baseline: 3.7382x; 1.4058x over previous
#include <cuda_runtime.h>
#include <cstdint>

// x (8,3,1024,1024) f32 -> out (8,3,512,512) f32
// d_in: [0]=x, [1]=w0 (K0*512), [2]=fov0 (K0*512 i32)  -> dim2 (H, vertical)
//       [3]=w1 (K1*512), [4]=fov1 (K1*512 i32)         -> dim3 (W, horizontal)
//
// R5: fused separable resize with ROLLING REGISTER WINDOW vertical pass.
// Each block validates (against the real fov0/w0 arrays) that its G output
// rows have contiguous windows sliding by 2 with oh-invariant weights; if so
// it loads each distinct input row exactly once into registers (24 rows vs
// 80 redundant reads), else it falls back to the generic gather loop.
// Horizontal pass: parity-split smem tile, conflict-free LDS (from R4).

#define BC     24
#define IN_H   1024
#define IN_W   1024
#define OUT_H  512
#define OUT_W  512
#define G      8           // output rows per block

// ---------------------------------------------------------------------------
template<int K>
__global__ __launch_bounds__(256)
void fused_roll_kernel(const float* __restrict__ x,
                       const float* __restrict__ w0,
                       const int*   __restrict__ fov0,
                       const float* __restrict__ w1,
                       const int*   __restrict__ fov1,
                       float*       __restrict__ out,
                       int K1)
{
    __shared__ float tile[G][IN_W];              // 32 KB, parity-permuted

    const int t   = threadIdx.x;                 // 0..255
    const int bc  = blockIdx.y;
    const int oh0 = blockIdx.x * G;

    const float4* xb = reinterpret_cast<const float4*>(x + (size_t)bc * IN_H * IN_W);

    // ---- regularity check: fov0[j][oh0+i] == start + 2i + j, w0 oh-invariant
    const int start = fov0[oh0];                 // fov0[0*OUT_H + oh0]
    int flag = 1;
    if (t < K * G) {
        const int j  = t / G;
        const int i  = t % G;
        const int oh = oh0 + i;
        flag  = (fov0[j * OUT_H + oh] == start + 2 * i + j);
        flag &= (w0  [j * OUT_H + oh] == w0[j * OUT_H + oh0]);
    }
    const int regular = __syncthreads_and(flag);

    if (regular) {
        // ---------- Phase 1a: rolling-window vertical resample ----------
        float wv[K];
#pragma unroll
        for (int j = 0; j < K; ++j) wv[j] = w0[j * OUT_H + oh0];

        float4 win[K];
#pragma unroll
        for (int j = 0; j < K; ++j)
            win[j] = xb[(size_t)(start + j) * (IN_W / 4) + t];

#pragma unroll
        for (int i = 0; i < G; ++i) {
            float ax = 0.f, ay = 0.f, az = 0.f, aw = 0.f;
#pragma unroll
            for (int j = 0; j < K; ++j) {
                ax += wv[j] * win[j].x;
                ay += wv[j] * win[j].y;
                az += wv[j] * win[j].z;
                aw += wv[j] * win[j].w;
            }
            float2 e; e.x = ax; e.y = az;
            float2 o; o.x = ay; o.y = aw;
            reinterpret_cast<float2*>(tile[i])[t]       = e;
            reinterpret_cast<float2*>(tile[i] + 512)[t] = o;

            if (i < G - 1) {
#pragma unroll
                for (int j = 0; j < K - 2; ++j) win[j] = win[j + 2];
                const int base = start + 2 * i + K;
                win[K - 2] = xb[(size_t)base       * (IN_W / 4) + t];
                win[K - 1] = xb[(size_t)(base + 1) * (IN_W / 4) + t];
            }
        }
    } else {
        // ---------- Phase 1b: generic gather (boundary blocks) ----------
        for (int i = 0; i < G; ++i) {
            const int oh = oh0 + i;
            float ax = 0.f, ay = 0.f, az = 0.f, aw = 0.f;
            for (int j = 0; j < K; ++j) {
                const int   r = fov0[j * OUT_H + oh];
                const float w = w0  [j * OUT_H + oh];
                const float4 v = xb[(size_t)r * (IN_W / 4) + t];
                ax += w * v.x;
                ay += w * v.y;
                az += w * v.z;
                aw += w * v.w;
            }
            float2 e; e.x = ax; e.y = az;
            float2 o; o.x = ay; o.y = aw;
            reinterpret_cast<float2*>(tile[i])[t]       = e;
            reinterpret_cast<float2*>(tile[i] + 512)[t] = o;
        }
    }
    __syncthreads();

    // ---------------- Phase 2: horizontal resample from permuted smem -------
    float a0[G], a1[G];
#pragma unroll
    for (int i = 0; i < G; ++i) { a0[i] = 0.f; a1[i] = 0.f; }

    for (int j = 0; j < K1; ++j) {
        const float w_a = w1  [j * OUT_W + t];
        const float w_b = w1  [j * OUT_W + t + 256];
        const int   f_a = fov1[j * OUT_W + t];
        const int   f_b = fov1[j * OUT_W + t + 256];
        const int p_a = (f_a >> 1) + ((f_a & 1) << 9);
        const int p_b = (f_b >> 1) + ((f_b & 1) << 9);
#pragma unroll
        for (int i = 0; i < G; ++i) {
            a0[i] += w_a * tile[i][p_a];
            a1[i] += w_b * tile[i][p_b];
        }
    }

#pragma unroll
    for (int i = 0; i < G; ++i) {
        float* orow = out + ((size_t)bc * OUT_H + oh0 + i) * OUT_W;
        orow[t]       = a0[i];
        orow[t + 256] = a1[i];
    }
}

// ---------------------------------------------------------------------------
// Generic fallback kernel (R4) for K0 outside the template set.
__global__ __launch_bounds__(256)
void fused_generic_kernel(const float* __restrict__ x,
                          const float* __restrict__ w0,
                          const int*   __restrict__ fov0,
                          const float* __restrict__ w1,
                          const int*   __restrict__ fov1,
                          float*       __restrict__ out,
                          int K0, int K1)
{
    __shared__ float tile[G][IN_W];
    const int t   = threadIdx.x;
    const int bc  = blockIdx.y;
    const int oh0 = blockIdx.x * G;
    const float4* xb = reinterpret_cast<const float4*>(x + (size_t)bc * IN_H * IN_W);

    for (int i = 0; i < G; ++i) {
        const int oh = oh0 + i;
        float ax = 0.f, ay = 0.f, az = 0.f, aw = 0.f;
        for (int j = 0; j < K0; ++j) {
            const int   r = fov0[j * OUT_H + oh];
            const float w = w0  [j * OUT_H + oh];
            const float4 v = xb[(size_t)r * (IN_W / 4) + t];
            ax += w * v.x; ay += w * v.y; az += w * v.z; aw += w * v.w;
        }
        float2 e; e.x = ax; e.y = az;
        float2 o; o.x = ay; o.y = aw;
        reinterpret_cast<float2*>(tile[i])[t]       = e;
        reinterpret_cast<float2*>(tile[i] + 512)[t] = o;
    }
    __syncthreads();

    float a0[G], a1[G];
#pragma unroll
    for (int i = 0; i < G; ++i) { a0[i] = 0.f; a1[i] = 0.f; }
    for (int j = 0; j < K1; ++j) {
        const float w_a = w1  [j * OUT_W + t];
        const float w_b = w1  [j * OUT_W + t + 256];
        const int   f_a = fov1[j * OUT_W + t];
        const int   f_b = fov1[j * OUT_W + t + 256];
        const int p_a = (f_a >> 1) + ((f_a & 1) << 9);
        const int p_b = (f_b >> 1) + ((f_b & 1) << 9);
#pragma unroll
        for (int i = 0; i < G; ++i) {
            a0[i] += w_a * tile[i][p_a];
            a1[i] += w_b * tile[i][p_b];
        }
    }
#pragma unroll
    for (int i = 0; i < G; ++i) {
        float* orow = out + ((size_t)bc * OUT_H + oh0 + i) * OUT_W;
        orow[t]       = a0[i];
        orow[t + 256] = a1[i];
    }
}

// ---------------------------------------------------------------------------

extern "C" void kernel_launch(void* const* d_in, const int* in_sizes, int n_in,
                              void* d_out, int out_size)
{
    const float* x    = (const float*)d_in[0];
    const float* w0   = (const float*)d_in[1];
    const int*   fov0 = (const int*)  d_in[2];
    const float* w1   = (const float*)d_in[3];
    const int*   fov1 = (const int*)  d_in[4];
    float*       out  = (float*)d_out;

    const int K0 = in_sizes[1] / OUT_H;   // vertical taps
    const int K1 = in_sizes[3] / OUT_W;   // horizontal taps

    dim3 grid(OUT_H / G, BC);

    switch (K0) {
    case 6:  fused_roll_kernel< 6><<<grid, 256>>>(x, w0, fov0, w1, fov1, out, K1); break;
    case 7:  fused_roll_kernel< 7><<<grid, 256>>>(x, w0, fov0, w1, fov1, out, K1); break;
    case 8:  fused_roll_kernel< 8><<<grid, 256>>>(x, w0, fov0, w1, fov1, out, K1); break;
    case 9:  fused_roll_kernel< 9><<<grid, 256>>>(x, w0, fov0, w1, fov1, out, K1); break;
    case 10: fused_roll_kernel<10><<<grid, 256>>>(x, w0, fov0, w1, fov1, out, K1); break;
    case 11: fused_roll_kernel<11><<<grid, 256>>>(x, w0, fov0, w1, fov1, out, K1); break;
    case 12: fused_roll_kernel<12><<<grid, 256>>>(x, w0, fov0, w1, fov1, out, K1); break;
    default: fused_generic_kernel<<<grid, 256>>>(x, w0, fov0, w1, fov1, out, K0, K1); break;
    }
}